// round 14
// baseline (speedup 1.0000x reference)
#include <cuda_runtime.h>

#define PNUM 32
#define INF  7
#define D2   64
#define OUTF 4096   // 2*D2*PNUM floats per voxel

// ---------- Kernel A: pin x into L2 (evict_last, pure-read phase) ----------
__global__ __launch_bounds__(128, 8)
void l2_pin_kernel(const ulonglong4* __restrict__ x8, int n8)
{
    const int stride = gridDim.x * blockDim.x;
    for (int i = blockIdx.x * blockDim.x + threadIdx.x; i < n8; i += stride) {
        unsigned long long a, b, c, d;
        asm volatile("ld.global.L2::evict_last.v4.b64 {%0,%1,%2,%3}, [%4];"
                     : "=l"(a), "=l"(b), "=l"(c), "=l"(d)
                     : "l"(x8 + i));
    }
}

// ---------- Kernel B: one voxel per block; minimal prologue ----------
__global__ __launch_bounds__(128, 8)
void vfe_kernel(const float* __restrict__ x,
                const float* __restrict__ W,
                const float* __restrict__ bias,
                float* __restrict__ out)
{
    __shared__ float sx[PNUM * 8];   // staged x, rows padded to 8
    __shared__ float sglob[D2];      // global feature vector

    const int t   = threadIdx.x;
    const int dg  = t & 15;          // dims [4*dg, 4*dg+4)
    const int pgr = t >> 4;          // points [4*pgr, 4*pgr+4)

    // Register-resident weights + bias for this thread's 4 dims.
    float w[4][INF], bb[4];
    #pragma unroll
    for (int k = 0; k < 4; k++) {
        const int d = dg * 4 + k;
        bb[k] = bias[d];
        #pragma unroll
        for (int i = 0; i < INF; i++) w[k][i] = W[d * INF + i];
    }

    const int v = blockIdx.x;

    // Read burst: this voxel's x (224 floats) from pinned L2.
    {
        const float* xv = x + (size_t)v * (PNUM * INF);
        #pragma unroll
        for (int q = 0; q < 2; q++) {
            const int idx = t + q * 128;          // 0..255
            if (idx < PNUM * INF) {
                const float val = __ldcg(xv + idx);
                const int r = idx / INF;
                sx[r * 8 + (idx - r * INF)] = val;
            }
        }
    }
    __syncthreads();

    float* ov = out + (size_t)v * OUTF;

    #pragma unroll
    for (int j = 0; j < 4; j++) {
        const int p = pgr * 4 + j;
        const float4 a0 = *(const float4*)(sx + p * 8);
        const float4 a1 = *(const float4*)(sx + p * 8 + 4);

        float acc[4];
        #pragma unroll
        for (int k = 0; k < 4; k++) {
            float a = bb[k];
            a = fmaf(a0.x, w[k][0], a);
            a = fmaf(a0.y, w[k][1], a);
            a = fmaf(a0.z, w[k][2], a);
            a = fmaf(a0.w, w[k][3], a);
            a = fmaf(a1.x, w[k][4], a);
            a = fmaf(a1.y, w[k][5], a);
            a = fmaf(a1.z, w[k][6], a);
            acc[k] = a;
        }

        // Local half of row p: coalesced streaming (evict-first) STG.128.
        __stcs((float4*)(ov + p * 128 + dg * 4),
               make_float4(acc[0], acc[1], acc[2], acc[3]));

        // Half-row max over this 8-lane group.
        float m = fmaxf(fmaxf(acc[0], acc[1]), fmaxf(acc[2], acc[3]));
        m = fmaxf(m, __shfl_xor_sync(0xffffffffu, m, 1));
        m = fmaxf(m, __shfl_xor_sync(0xffffffffu, m, 2));
        m = fmaxf(m, __shfl_xor_sync(0xffffffffu, m, 4));
        if ((t & 7) == 0)
            sglob[2 * p + ((t >> 3) & 1)] = m;
    }

    __syncthreads();   // publish sglob

    // Broadcast half of every row (same coalesced streaming pattern).
    const float4 gv = *(const float4*)(sglob + dg * 4);
    #pragma unroll
    for (int j = 0; j < 4; j++) {
        const int p = pgr * 4 + j;
        __stcs((float4*)(ov + p * 128 + 64 + dg * 4), gv);
    }
}

extern "C" void kernel_launch(void* const* d_in, const int* in_sizes, int n_in,
                              void* d_out, int out_size)
{
    const float* x = (const float*)d_in[0];
    const float* W = (const float*)d_in[1];
    const float* b = (const float*)d_in[2];
    float* out     = (float*)d_out;

    const int B  = in_sizes[0] / (PNUM * INF);      // 32768
    const int n8 = in_sizes[0] / 8;                 // x as 32B chunks

    // Phase 1: pin x (29 MB) into L2 with evict_last.
    l2_pin_kernel<<<2048, 128>>>((const ulonglong4*)x, n8);

    // Phase 2: one voxel per block; stores evict-first, reads from pinned L2.
    vfe_kernel<<<B, 128>>>(x, W, b, out);
}

// round 15
// speedup vs baseline: 1.1007x; 1.1007x over previous
#include <cuda_runtime.h>

#define PNUM 32
#define INF  7
#define D2   64
#define OUTF 4096   // 2*D2*PNUM floats per voxel
#define VPB  2      // voxels per block

__global__ __launch_bounds__(128, 8)
void vfe_kernel(const float* __restrict__ x,
                const float* __restrict__ W,
                const float* __restrict__ bias,
                float* __restrict__ out,
                int B)
{
    __shared__ float sx[VPB][PNUM * 8];  // staged x, rows padded to 8
    __shared__ float sglob[2][D2];       // parity double-buffered global vector

    const int t   = threadIdx.x;
    const int dg  = t & 15;              // dims [4*dg, 4*dg+4)
    const int pgr = t >> 4;              // points [4*pgr, 4*pgr+4)

    // Register-resident weights + bias for this thread's 4 dims.
    float w[4][INF], bb[4];
    #pragma unroll
    for (int k = 0; k < 4; k++) {
        const int d = dg * 4 + k;
        bb[k] = bias[d];
        #pragma unroll
        for (int i = 0; i < INF; i++) w[k][i] = W[d * INF + i];
    }

    const int v0   = blockIdx.x * VPB;
    const int nvox = min(VPB, B - v0);
    float* sxf = &sx[0][0];

    // Read burst: both voxels' x (448 floats). __ldcg = default L2 priority,
    // so x stays L2-resident across graph replays while the evict-first
    // write stream (__stcs) is preferentially evicted around it.
    {
        const float* xv = x + (size_t)v0 * (PNUM * INF);
        const int lim = nvox * PNUM * INF;
        #pragma unroll
        for (int q = 0; q < 4; q++) {
            const int idx = t + q * 128;          // 0..511
            if (idx < lim) {
                const float val = __ldcg(xv + idx);
                const int r = idx / INF;
                sxf[r * 8 + (idx - r * INF)] = val;
            }
        }
    }
    __syncthreads();

    #pragma unroll 1
    for (int it = 0; it < nvox; it++) {
        const int c = it & 1;
        float* ov = out + (size_t)(v0 + it) * OUTF;
        const float* sxv = &sx[it][0];

        #pragma unroll
        for (int j = 0; j < 4; j++) {
            const int p = pgr * 4 + j;
            const float4 a0 = *(const float4*)(sxv + p * 8);
            const float4 a1 = *(const float4*)(sxv + p * 8 + 4);

            float acc[4];
            #pragma unroll
            for (int k = 0; k < 4; k++) {
                float a = bb[k];
                a = fmaf(a0.x, w[k][0], a);
                a = fmaf(a0.y, w[k][1], a);
                a = fmaf(a0.z, w[k][2], a);
                a = fmaf(a0.w, w[k][3], a);
                a = fmaf(a1.x, w[k][4], a);
                a = fmaf(a1.y, w[k][5], a);
                a = fmaf(a1.z, w[k][6], a);
                acc[k] = a;
            }

            // Local half of row p: coalesced streaming (evict-first) STG.128.
            __stcs((float4*)(ov + p * 128 + dg * 4),
                   make_float4(acc[0], acc[1], acc[2], acc[3]));

            // Half-row max over this 8-lane group.
            float m = fmaxf(fmaxf(acc[0], acc[1]), fmaxf(acc[2], acc[3]));
            m = fmaxf(m, __shfl_xor_sync(0xffffffffu, m, 1));
            m = fmaxf(m, __shfl_xor_sync(0xffffffffu, m, 2));
            m = fmaxf(m, __shfl_xor_sync(0xffffffffu, m, 4));
            if ((t & 7) == 0)
                sglob[c][2 * p + ((t >> 3) & 1)] = m;
        }

        __syncthreads();   // publish sglob[c]

        // Broadcast half of every row (same coalesced streaming pattern).
        const float4 gv = *(const float4*)(&sglob[c][dg * 4]);
        #pragma unroll
        for (int j = 0; j < 4; j++) {
            const int p = pgr * 4 + j;
            __stcs((float4*)(ov + p * 128 + 64 + dg * 4), gv);
        }
    }
}

extern "C" void kernel_launch(void* const* d_in, const int* in_sizes, int n_in,
                              void* d_out, int out_size)
{
    const float* x = (const float*)d_in[0];
    const float* W = (const float*)d_in[1];
    const float* b = (const float*)d_in[2];
    float* out     = (float*)d_out;

    const int B = in_sizes[0] / (PNUM * INF);       // 32768
    const int grid = (B + VPB - 1) / VPB;           // 16384
    vfe_kernel<<<grid, 128>>>(x, W, b, out, B);
}